// round 3
// baseline (speedup 1.0000x reference)
#include <cuda_runtime.h>
#include <cstdint>

#define UNUM 100000
#define INUM 200000
#define NTOT 300000
#define NNZE 4000000
#define BSZ  4096
#define DIM  64
#define NLAY 3
#define CDIM (DIM*(NLAY+1))   // 256

// ---------------- scratch (static device globals; no allocs allowed) ----------------
__device__ __align__(256) float g_ego [(size_t)NTOT * DIM];          // 76.8 MB
__device__ __align__(256) float g_side[(size_t)NTOT * DIM];          // 76.8 MB
__device__ __align__(256) float g_all [(size_t)NTOT * CDIM];         // 307 MB
__device__ __align__(256) float g_vald[NNZE];                        // 16 MB
__device__ float g_acc[2];                                           // bpr_sum, reg_sum

// ---------------- threefry2x32 (exact JAX semantics) ----------------
__host__ __device__ __forceinline__ uint32_t rotl32(uint32_t x, int r) {
    return (x << r) | (x >> (32 - r));
}

__host__ __device__ inline void threefry2x32(uint32_t k0, uint32_t k1,
                                             uint32_t x0, uint32_t x1,
                                             uint32_t &o0, uint32_t &o1) {
    uint32_t k2 = k0 ^ k1 ^ 0x1BD11BDAu;
    x0 += k0; x1 += k1;
#define TF_R(r) { x0 += x1; x1 = rotl32(x1, r); x1 ^= x0; }
    TF_R(13) TF_R(15) TF_R(26) TF_R(6)   x0 += k1; x1 += k2 + 1u;
    TF_R(17) TF_R(29) TF_R(16) TF_R(24)  x0 += k2; x1 += k0 + 2u;
    TF_R(13) TF_R(15) TF_R(26) TF_R(6)   x0 += k0; x1 += k1 + 3u;
    TF_R(17) TF_R(29) TF_R(16) TF_R(24)  x0 += k1; x1 += k2 + 4u;
    TF_R(13) TF_R(15) TF_R(26) TF_R(6)   x0 += k2; x1 += k0 + 5u;
#undef TF_R
    o0 = x0; o1 = x1;
}

// Partitionable (counter-mode) random bits, JAX >= 0.4.36 default:
// counter = uint64 i -> threefry(key, (hi32=0, lo32=i)); 32-bit finisher = o0 ^ o1
__device__ __forceinline__ uint32_t rbits_partitionable(uint32_t k0, uint32_t k1, uint32_t i) {
    uint32_t o0, o1;
    threefry2x32(k0, k1, 0u, i, o0, o1);
    return o0 ^ o1;
}

__device__ __forceinline__ float u01(uint32_t bits) {
    // exact JAX uniform: bitcast((bits>>9)|0x3f800000) - 1
    return __uint_as_float((bits >> 9) | 0x3F800000u) - 1.0f;
}

// ---------------- kernels ----------------
__global__ void init_kernel(const float* __restrict__ ue, const float* __restrict__ ie) {
    int i = blockIdx.x * blockDim.x + threadIdx.x;
    if (i == 0) { g_acc[0] = 0.f; g_acc[1] = 0.f; }
    if (i >= NTOT * DIM) return;
    int nrow = i >> 6, d = i & 63;
    float v = (nrow < UNUM) ? ue[i] : ie[i - UNUM * DIM];
    g_ego[i] = v;
    g_all[(size_t)nrow * CDIM + d] = v;   // layer-0 block is NOT normalized
}

__global__ void edgedrop_kernel(const float* __restrict__ val, uint32_t k0, uint32_t k1) {
    int i = blockIdx.x * blockDim.x + threadIdx.x;
    if (i >= NNZE) return;
    float u = u01(rbits_partitionable(k0, k1, (uint32_t)i));
    g_vald[i] = (u < 0.9f) ? val[i] * (1.0f / 0.9f) : 0.f;
}

// SpMM: 16 lanes per edge, one float4 each; vector atomics (sm_90+)
__global__ void spmm_kernel(const int* __restrict__ row, const int* __restrict__ col) {
    long long t = (long long)blockIdx.x * blockDim.x + threadIdx.x;
    int e = (int)(t >> 4);
    if (e >= NNZE) return;
    int lane = (int)(t & 15);
    float v = g_vald[e];
    if (v == 0.f) return;    // uniform across the 16-lane group
    int c = col[e], r = row[e];
    float4 x = ((const float4*)(g_ego + (size_t)c * DIM))[lane];
    x.x *= v; x.y *= v; x.z *= v; x.w *= v;
    atomicAdd(((float4*)(g_side + (size_t)r * DIM)) + lane, x);
}

// side@Wg + b_gc + (ego*side)@Wb + b_bi -> leaky_relu -> g_ego (in place)
// 256 threads / block, 64 rows / block, W + tiles in smem (65-pad vs bank conflicts)
__global__ void combine_kernel(const float* __restrict__ Wg, const float* __restrict__ bg,
                               const float* __restrict__ Wb, const float* __restrict__ bb) {
    extern __shared__ float sm[];
    float* sWg = sm;              // 4096
    float* sWb = sm + 4096;       // 4096
    float* sS  = sm + 8192;       // 64*65
    float* sE  = sS + 64 * 65;    // 64*65
    int tid = threadIdx.x;
    int row0 = blockIdx.x * 64;

    for (int i = tid; i < 4096; i += 256) { sWg[i] = Wg[i]; sWb[i] = Wb[i]; }
    for (int i = tid; i < 4096; i += 256) {
        int r = i >> 6, d = i & 63;
        int gr = row0 + r;
        float s = 0.f, e = 0.f;
        if (gr < NTOT) {
            s = g_side[(size_t)gr * DIM + d];
            e = g_ego [(size_t)gr * DIM + d];
        }
        sS[r * 65 + d] = s;
        sE[r * 65 + d] = e;
    }
    __syncthreads();

    int r  = tid & 63;
    int cg = tid >> 6;            // 0..3
    int c0 = cg * 16;
    float acc[16];
#pragma unroll
    for (int c = 0; c < 16; c++) acc[c] = bg[c0 + c] + bb[c0 + c];

    for (int j = 0; j < 64; j++) {
        float s  = sS[r * 65 + j];
        float es = sE[r * 65 + j] * s;
        const float* wg = &sWg[j * 64 + c0];
        const float* wb = &sWb[j * 64 + c0];
#pragma unroll
        for (int c = 0; c < 16; c++) acc[c] += s * wg[c] + es * wb[c];
    }

    int gr = row0 + r;
    if (gr < NTOT) {
        float4* dst = (float4*)(g_ego + (size_t)gr * DIM + c0);
#pragma unroll
        for (int q = 0; q < 4; q++) {
            float a = acc[4*q+0], b = acc[4*q+1], c2 = acc[4*q+2], d = acc[4*q+3];
            a  = (a  >= 0.f) ? a  : 0.2f * a;
            b  = (b  >= 0.f) ? b  : 0.2f * b;
            c2 = (c2 >= 0.f) ? c2 : 0.2f * c2;
            d  = (d  >= 0.f) ? d  : 0.2f * d;
            dst[q] = make_float4(a, b, c2, d);
        }
    }
}

// Fused: message dropout (counter-mode threefry) + row L2 normalize.
// Warp per row; dropped un-normalized ego -> g_ego (next layer input),
// normalized -> g_all concat block.
__global__ void msgnorm_kernel(uint32_t k0, uint32_t k1, int layer) {
    int w    = (blockIdx.x * blockDim.x + threadIdx.x) >> 5;
    int lane = threadIdx.x & 31;
    if (w >= NTOT) return;
    size_t base = (size_t)w * DIM;
    float2 v = ((const float2*)(g_ego + base))[lane];
    uint32_t i0 = (uint32_t)base + (uint32_t)(lane * 2);
    float u0 = u01(rbits_partitionable(k0, k1, i0));
    float u1 = u01(rbits_partitionable(k0, k1, i0 + 1u));
    v.x = (u0 < 0.9f) ? v.x * (1.0f / 0.9f) : 0.f;
    v.y = (u1 < 0.9f) ? v.y * (1.0f / 0.9f) : 0.f;
    ((float2*)(g_ego + base))[lane] = v;

    float ss = v.x * v.x + v.y * v.y;
#pragma unroll
    for (int o = 16; o; o >>= 1) ss += __shfl_xor_sync(0xFFFFFFFFu, ss, o);
    float denom = fmaxf(sqrtf(ss), 1e-12f);
    float inv = 1.0f / denom;
    float* dst = g_all + (size_t)w * CDIM + (size_t)(layer + 1) * DIM;
    ((float2*)dst)[lane] = make_float2(v.x * inv, v.y * inv);
}

// warp per sample: BPR + reg partial sums
__global__ void loss_kernel(const float* __restrict__ ue0, const float* __restrict__ ie0,
                            const int* __restrict__ uid, const int* __restrict__ pid,
                            const int* __restrict__ nid) {
    int w    = (blockIdx.x * blockDim.x + threadIdx.x) >> 5;
    int lane = threadIdx.x & 31;
    if (w >= BSZ) return;
    int u = uid[w], p = pid[w], n = nid[w];
    const float4* ua = (const float4*)(g_all + (size_t)u * CDIM);
    const float4* pa = (const float4*)(g_all + (size_t)(UNUM + p) * CDIM);
    const float4* na = (const float4*)(g_all + (size_t)(UNUM + n) * CDIM);
    float pos = 0.f, neg = 0.f;
#pragma unroll
    for (int t = 0; t < 2; t++) {
        float4 a = ua[lane * 2 + t], b = pa[lane * 2 + t], c = na[lane * 2 + t];
        pos += a.x * b.x + a.y * b.y + a.z * b.z + a.w * b.w;
        neg += a.x * c.x + a.y * c.y + a.z * c.z + a.w * c.w;
    }
    float2 a0 = ((const float2*)(ue0 + (size_t)u * DIM))[lane];
    float2 b0 = ((const float2*)(ie0 + (size_t)p * DIM))[lane];
    float2 c0 = ((const float2*)(ie0 + (size_t)n * DIM))[lane];
    float rg = a0.x * a0.x + a0.y * a0.y + b0.x * b0.x + b0.y * b0.y + c0.x * c0.x + c0.y * c0.y;
#pragma unroll
    for (int o = 16; o; o >>= 1) {
        pos += __shfl_xor_sync(0xFFFFFFFFu, pos, o);
        neg += __shfl_xor_sync(0xFFFFFFFFu, neg, o);
        rg  += __shfl_xor_sync(0xFFFFFFFFu, rg,  o);
    }
    if (lane == 0) {
        float x = pos - neg;
        float ls = fminf(x, 0.f) - log1pf(expf(-fabsf(x)));  // stable log_sigmoid
        atomicAdd(&g_acc[0], ls);
        atomicAdd(&g_acc[1], rg);
    }
}

__global__ void fin_kernel(float* out, int osz) {
    float bpr = -g_acc[0] / (float)BSZ;
    float reg = 1e-4f * 0.5f * g_acc[1] / (float)BSZ;
    if (osz >= 3) { out[0] = bpr + reg; out[1] = bpr; out[2] = reg; }
    else          { out[0] = bpr + reg; }
}

// ---------------- launch ----------------
extern "C" void kernel_launch(void* const* d_in, const int* in_sizes, int n_in,
                              void* d_out, int out_size) {
    const float* user_emb = (const float*)d_in[0];
    const float* item_emb = (const float*)d_in[1];
    const float* W_gc     = (const float*)d_in[2];
    const float* b_gc     = (const float*)d_in[3];
    const float* W_bi     = (const float*)d_in[4];
    const float* b_bi     = (const float*)d_in[5];
    const float* val      = (const float*)d_in[6];
    const int*   row      = (const int*)d_in[7];
    const int*   col      = (const int*)d_in[8];
    const int*   uid      = (const int*)d_in[9];
    const int*   pid      = (const int*)d_in[10];
    const int*   nid      = (const int*)d_in[11];

    // derived threefry keys: base key = (0, 42); fold_in(data) = threefry(key, (0, data))
    uint32_t ke0, ke1;
    threefry2x32(0u, 42u, 0u, 0u, ke0, ke1);

    cudaFuncSetAttribute(combine_kernel, cudaFuncAttributeMaxDynamicSharedMemorySize, 66048);
    void* side_ptr = nullptr;
    cudaGetSymbolAddress(&side_ptr, g_side);

    init_kernel<<<(NTOT * DIM + 255) / 256, 256>>>(user_emb, item_emb);
    edgedrop_kernel<<<(NNZE + 255) / 256, 256>>>(val, ke0, ke1);

    for (int k = 0; k < NLAY; k++) {
        cudaMemsetAsync(side_ptr, 0, (size_t)NTOT * DIM * sizeof(float));
        spmm_kernel<<<(int)(((long long)NNZE * 16 + 255) / 256), 256>>>(row, col);
        combine_kernel<<<(NTOT + 63) / 64, 256, 66048>>>(W_gc + k * 4096, b_gc + k * 64,
                                                         W_bi + k * 4096, b_bi + k * 64);
        uint32_t km0, km1;
        threefry2x32(0u, 42u, 0u, (uint32_t)(k + 1), km0, km1);
        msgnorm_kernel<<<(NTOT * 32 + 255) / 256, 256>>>(km0, km1, k);
    }

    loss_kernel<<<(BSZ * 32 + 255) / 256, 256>>>(user_emb, item_emb, uid, pid, nid);
    fin_kernel<<<1, 1>>>((float*)d_out, out_size);
}

// round 4
// speedup vs baseline: 1.6849x; 1.6849x over previous
#include <cuda_runtime.h>
#include <cstdint>

#define UNUM 100000
#define INUM 200000
#define NTOT 300000
#define NNZE 4000000
#define BSZ  4096
#define DIM  64
#define NLAY 3
#define CDIM (DIM*(NLAY+1))   // 256
#define EMAX 96               // padded ELL row capacity (mean deg ~12)

// ---------------- scratch (static device globals; no allocs allowed) ----------------
__device__ __align__(256) float g_ego [(size_t)NTOT * DIM];          // 76.8 MB
__device__ __align__(256) float g_side[(size_t)NTOT * DIM];          // 76.8 MB
__device__ __align__(256) float g_all [(size_t)NTOT * CDIM];         // 307 MB
__device__ __align__(256) int2  g_ell [(size_t)NTOT * EMAX];         // 230 MB {col, val bits}
__device__ __align__(256) int   g_cnt [NTOT];
__device__ float g_acc[2];                                           // bpr_sum, reg_sum

// ---------------- threefry2x32 (exact JAX semantics) ----------------
__host__ __device__ __forceinline__ uint32_t rotl32(uint32_t x, int r) {
    return (x << r) | (x >> (32 - r));
}

__host__ __device__ inline void threefry2x32(uint32_t k0, uint32_t k1,
                                             uint32_t x0, uint32_t x1,
                                             uint32_t &o0, uint32_t &o1) {
    uint32_t k2 = k0 ^ k1 ^ 0x1BD11BDAu;
    x0 += k0; x1 += k1;
#define TF_R(r) { x0 += x1; x1 = rotl32(x1, r); x1 ^= x0; }
    TF_R(13) TF_R(15) TF_R(26) TF_R(6)   x0 += k1; x1 += k2 + 1u;
    TF_R(17) TF_R(29) TF_R(16) TF_R(24)  x0 += k2; x1 += k0 + 2u;
    TF_R(13) TF_R(15) TF_R(26) TF_R(6)   x0 += k0; x1 += k1 + 3u;
    TF_R(17) TF_R(29) TF_R(16) TF_R(24)  x0 += k1; x1 += k2 + 4u;
    TF_R(13) TF_R(15) TF_R(26) TF_R(6)   x0 += k2; x1 += k0 + 5u;
#undef TF_R
    o0 = x0; o1 = x1;
}

// Partitionable (counter-mode) bits: threefry(key, (0, i)), 32-bit finisher o0^o1
__device__ __forceinline__ uint32_t rbits_partitionable(uint32_t k0, uint32_t k1, uint32_t i) {
    uint32_t o0, o1;
    threefry2x32(k0, k1, 0u, i, o0, o1);
    return o0 ^ o1;
}

__device__ __forceinline__ float u01(uint32_t bits) {
    return __uint_as_float((bits >> 9) | 0x3F800000u) - 1.0f;
}

// ---------------- kernels ----------------
__global__ void init_kernel(const float* __restrict__ ue, const float* __restrict__ ie) {
    int i = blockIdx.x * blockDim.x + threadIdx.x;
    if (i == 0) { g_acc[0] = 0.f; g_acc[1] = 0.f; }
    if (i >= NTOT * DIM) return;
    int nrow = i >> 6, d = i & 63;
    float v = (nrow < UNUM) ? ue[i] : ie[i - UNUM * DIM];
    g_ego[i] = v;
    g_all[(size_t)nrow * CDIM + d] = v;   // layer-0 block is NOT normalized
}

// One pass: edge dropout + ELL scatter (dropped edges never stored).
__global__ void scatter_kernel(const float* __restrict__ val, const int* __restrict__ row,
                               const int* __restrict__ col, uint32_t k0, uint32_t k1) {
    int e = blockIdx.x * blockDim.x + threadIdx.x;
    if (e >= NNZE) return;
    float u = u01(rbits_partitionable(k0, k1, (uint32_t)e));
    if (u >= 0.9f) return;                 // dropped: contributes +0 exactly
    float v = val[e] * (1.0f / 0.9f);
    int r = row[e];
    int pos = atomicAdd(&g_cnt[r], 1);
    if (pos < EMAX)
        g_ell[(size_t)r * EMAX + pos] = make_int2(col[e], __float_as_int(v));
}

// Atomic-free SpMM: one warp per row; 2 edge-slots x 16 dim-lanes.
__global__ void spmm_kernel() {
    int w    = (blockIdx.x * blockDim.x + threadIdx.x) >> 5;
    if (w >= NTOT) return;
    int lane = threadIdx.x & 31;
    int sub  = lane >> 4;       // which edge slot
    int dl   = lane & 15;       // dim quarter (float4)
    int cnt  = g_cnt[w];
    if (cnt > EMAX) cnt = EMAX;
    const int2* ep = g_ell + (size_t)w * EMAX;
    float4 acc = make_float4(0.f, 0.f, 0.f, 0.f);
    for (int j = sub; j < cnt; j += 2) {
        int2 cv = ep[j];
        float v = __int_as_float(cv.y);
        float4 x = ((const float4*)(g_ego + (size_t)cv.x * DIM))[dl];
        acc.x += v * x.x; acc.y += v * x.y; acc.z += v * x.z; acc.w += v * x.w;
    }
    acc.x += __shfl_xor_sync(0xFFFFFFFFu, acc.x, 16);
    acc.y += __shfl_xor_sync(0xFFFFFFFFu, acc.y, 16);
    acc.z += __shfl_xor_sync(0xFFFFFFFFu, acc.z, 16);
    acc.w += __shfl_xor_sync(0xFFFFFFFFu, acc.w, 16);
    if (sub == 0)
        ((float4*)(g_side + (size_t)w * DIM))[dl] = acc;
}

// side@Wg + b_gc + (ego*side)@Wb + b_bi -> leaky_relu -> g_ego (in place)
// 256 threads / block, 128 rows / block, 2 rows x 16 cols per thread.
// S/E stored in two planes (even/odd rows) so both per-j row reads are stride-65
// conflict-free; W reads are warp-uniform broadcasts.
__global__ void combine_kernel(const float* __restrict__ Wg, const float* __restrict__ bg,
                               const float* __restrict__ Wb, const float* __restrict__ bb) {
    extern __shared__ float sm[];
    float* sWg = sm;                      // 4096
    float* sWb = sm + 4096;               // 4096
    float* sS  = sm + 8192;               // 2 planes x 64 x 65
    float* sE  = sS + 2 * 64 * 65;        // 2 planes x 64 x 65
    const int PL = 64 * 65;
    int tid  = threadIdx.x;
    int row0 = blockIdx.x * 128;

    for (int i = tid; i < 4096; i += 256) { sWg[i] = Wg[i]; sWb[i] = Wb[i]; }
    for (int i = tid; i < 128 * 16; i += 256) {     // float4 granularity
        int r = i >> 4, q = i & 15;
        int gr = row0 + r;
        float4 s = make_float4(0.f, 0.f, 0.f, 0.f), e = s;
        if (gr < NTOT) {
            s = ((const float4*)(g_side + (size_t)gr * DIM))[q];
            e = ((const float4*)(g_ego  + (size_t)gr * DIM))[q];
        }
        int p = r & 1, rp = r >> 1;
        float* ds = &sS[p * PL + rp * 65 + q * 4];
        float* de = &sE[p * PL + rp * 65 + q * 4];
        ds[0] = s.x; ds[1] = s.y; ds[2] = s.z; ds[3] = s.w;
        de[0] = e.x; de[1] = e.y; de[2] = e.z; de[3] = e.w;
    }
    __syncthreads();

    int cg = tid >> 6;           // 0..3 column group (warp-uniform)
    int rp = tid & 63;           // row pair
    int c0 = cg * 16;
    float acc0[16], acc1[16];
#pragma unroll
    for (int c = 0; c < 16; c++) {
        float b = bg[c0 + c] + bb[c0 + c];
        acc0[c] = b; acc1[c] = b;
    }

    for (int j = 0; j < 64; j++) {
        float s0 = sS[rp * 65 + j];
        float s1 = sS[PL + rp * 65 + j];
        float es0 = sE[rp * 65 + j] * s0;
        float es1 = sE[PL + rp * 65 + j] * s1;
        const float4* wg4 = (const float4*)&sWg[j * 64 + c0];
        const float4* wb4 = (const float4*)&sWb[j * 64 + c0];
#pragma unroll
        for (int q = 0; q < 4; q++) {
            float4 wg = wg4[q], wb = wb4[q];
            acc0[4*q+0] += s0 * wg.x + es0 * wb.x;
            acc0[4*q+1] += s0 * wg.y + es0 * wb.y;
            acc0[4*q+2] += s0 * wg.z + es0 * wb.z;
            acc0[4*q+3] += s0 * wg.w + es0 * wb.w;
            acc1[4*q+0] += s1 * wg.x + es1 * wb.x;
            acc1[4*q+1] += s1 * wg.y + es1 * wb.y;
            acc1[4*q+2] += s1 * wg.z + es1 * wb.z;
            acc1[4*q+3] += s1 * wg.w + es1 * wb.w;
        }
    }

#pragma unroll
    for (int p = 0; p < 2; p++) {
        int gr = row0 + rp * 2 + p;
        if (gr >= NTOT) continue;
        float* accp = p ? acc1 : acc0;
        float4* dst = (float4*)(g_ego + (size_t)gr * DIM + c0);
#pragma unroll
        for (int q = 0; q < 4; q++) {
            float a = accp[4*q+0], b = accp[4*q+1], c2 = accp[4*q+2], d = accp[4*q+3];
            a  = (a  >= 0.f) ? a  : 0.2f * a;
            b  = (b  >= 0.f) ? b  : 0.2f * b;
            c2 = (c2 >= 0.f) ? c2 : 0.2f * c2;
            d  = (d  >= 0.f) ? d  : 0.2f * d;
            dst[q] = make_float4(a, b, c2, d);
        }
    }
}

// Fused: message dropout (counter-mode threefry) + row L2 normalize.
__global__ void msgnorm_kernel(uint32_t k0, uint32_t k1, int layer) {
    int w    = (blockIdx.x * blockDim.x + threadIdx.x) >> 5;
    int lane = threadIdx.x & 31;
    if (w >= NTOT) return;
    size_t base = (size_t)w * DIM;
    float2 v = ((const float2*)(g_ego + base))[lane];
    uint32_t i0 = (uint32_t)base + (uint32_t)(lane * 2);
    float u0 = u01(rbits_partitionable(k0, k1, i0));
    float u1 = u01(rbits_partitionable(k0, k1, i0 + 1u));
    v.x = (u0 < 0.9f) ? v.x * (1.0f / 0.9f) : 0.f;
    v.y = (u1 < 0.9f) ? v.y * (1.0f / 0.9f) : 0.f;
    ((float2*)(g_ego + base))[lane] = v;

    float ss = v.x * v.x + v.y * v.y;
#pragma unroll
    for (int o = 16; o; o >>= 1) ss += __shfl_xor_sync(0xFFFFFFFFu, ss, o);
    float denom = fmaxf(sqrtf(ss), 1e-12f);
    float inv = 1.0f / denom;
    float* dst = g_all + (size_t)w * CDIM + (size_t)(layer + 1) * DIM;
    ((float2*)dst)[lane] = make_float2(v.x * inv, v.y * inv);
}

// warp per sample: BPR + reg partial sums
__global__ void loss_kernel(const float* __restrict__ ue0, const float* __restrict__ ie0,
                            const int* __restrict__ uid, const int* __restrict__ pid,
                            const int* __restrict__ nid) {
    int w    = (blockIdx.x * blockDim.x + threadIdx.x) >> 5;
    int lane = threadIdx.x & 31;
    if (w >= BSZ) return;
    int u = uid[w], p = pid[w], n = nid[w];
    const float4* ua = (const float4*)(g_all + (size_t)u * CDIM);
    const float4* pa = (const float4*)(g_all + (size_t)(UNUM + p) * CDIM);
    const float4* na = (const float4*)(g_all + (size_t)(UNUM + n) * CDIM);
    float pos = 0.f, neg = 0.f;
#pragma unroll
    for (int t = 0; t < 2; t++) {
        float4 a = ua[lane * 2 + t], b = pa[lane * 2 + t], c = na[lane * 2 + t];
        pos += a.x * b.x + a.y * b.y + a.z * b.z + a.w * b.w;
        neg += a.x * c.x + a.y * c.y + a.z * c.z + a.w * c.w;
    }
    float2 a0 = ((const float2*)(ue0 + (size_t)u * DIM))[lane];
    float2 b0 = ((const float2*)(ie0 + (size_t)p * DIM))[lane];
    float2 c0 = ((const float2*)(ie0 + (size_t)n * DIM))[lane];
    float rg = a0.x * a0.x + a0.y * a0.y + b0.x * b0.x + b0.y * b0.y + c0.x * c0.x + c0.y * c0.y;
#pragma unroll
    for (int o = 16; o; o >>= 1) {
        pos += __shfl_xor_sync(0xFFFFFFFFu, pos, o);
        neg += __shfl_xor_sync(0xFFFFFFFFu, neg, o);
        rg  += __shfl_xor_sync(0xFFFFFFFFu, rg,  o);
    }
    if (lane == 0) {
        float x = pos - neg;
        float ls = fminf(x, 0.f) - log1pf(expf(-fabsf(x)));  // stable log_sigmoid
        atomicAdd(&g_acc[0], ls);
        atomicAdd(&g_acc[1], rg);
    }
}

__global__ void fin_kernel(float* out, int osz) {
    float bpr = -g_acc[0] / (float)BSZ;
    float reg = 1e-4f * 0.5f * g_acc[1] / (float)BSZ;
    if (osz >= 3) { out[0] = bpr + reg; out[1] = bpr; out[2] = reg; }
    else          { out[0] = bpr + reg; }
}

// ---------------- launch ----------------
extern "C" void kernel_launch(void* const* d_in, const int* in_sizes, int n_in,
                              void* d_out, int out_size) {
    const float* user_emb = (const float*)d_in[0];
    const float* item_emb = (const float*)d_in[1];
    const float* W_gc     = (const float*)d_in[2];
    const float* b_gc     = (const float*)d_in[3];
    const float* W_bi     = (const float*)d_in[4];
    const float* b_bi     = (const float*)d_in[5];
    const float* val      = (const float*)d_in[6];
    const int*   row      = (const int*)d_in[7];
    const int*   col      = (const int*)d_in[8];
    const int*   uid      = (const int*)d_in[9];
    const int*   pid      = (const int*)d_in[10];
    const int*   nid      = (const int*)d_in[11];

    // derived threefry keys: base key = (0, 42); fold_in(d) = threefry(key, (0, d))
    uint32_t ke0, ke1;
    threefry2x32(0u, 42u, 0u, 0u, ke0, ke1);

    static bool attr_set = false;
    if (!attr_set) {
        cudaFuncSetAttribute(combine_kernel, cudaFuncAttributeMaxDynamicSharedMemorySize,
                             (8192 + 4 * 64 * 65) * sizeof(float));
        attr_set = true;
    }
    void* cnt_ptr = nullptr;
    cudaGetSymbolAddress(&cnt_ptr, g_cnt);

    init_kernel<<<(NTOT * DIM + 255) / 256, 256>>>(user_emb, item_emb);
    cudaMemsetAsync(cnt_ptr, 0, NTOT * sizeof(int));
    scatter_kernel<<<(NNZE + 255) / 256, 256>>>(val, row, col, ke0, ke1);

    for (int k = 0; k < NLAY; k++) {
        spmm_kernel<<<(NTOT * 32 + 255) / 256, 256>>>();
        combine_kernel<<<(NTOT + 127) / 128, 256,
                         (8192 + 4 * 64 * 65) * sizeof(float)>>>(
            W_gc + k * 4096, b_gc + k * 64, W_bi + k * 4096, b_bi + k * 64);
        uint32_t km0, km1;
        threefry2x32(0u, 42u, 0u, (uint32_t)(k + 1), km0, km1);
        msgnorm_kernel<<<(NTOT * 32 + 255) / 256, 256>>>(km0, km1, k);
    }

    loss_kernel<<<(BSZ * 32 + 255) / 256, 256>>>(user_emb, item_emb, uid, pid, nid);
    fin_kernel<<<1, 1>>>((float*)d_out, out_size);
}